// round 14
// baseline (speedup 1.0000x reference)
#include <cuda_runtime.h>
#include <cuda_fp16.h>
#include <cstdint>

// ============================================================================
// DirectionalConv3d via mma.sync FP16 (compute_103-safe).
//   x: [8, 64, 32, 32, 32] fp32; 7 weights [64,64]; out[b,o,n] =
//     sum_d sum_i W_d[o,i] * x[b,i, n+shift_d]   (zero outside domain)
//
// R13 change vs R12 (84.0us; k_gemm flat at 61-65us, all pipes <65%, occ 8
// warps/SM): occupancy attack. 128-thread CTAs with __launch_bounds__(128,3)
// -> 12 warps/SM (reg target <=170), simple rolled direction loop (R9
// structure, best measured) + R12's closed-form addressing via __constant__
// tables. Persistent grid 444 (=148*3), stride over 1024 tiles (256 pts each).
// k_prep: float4 global reads (4x fewer LDG instrs).
//
// x scratch layout (uint4 units):  g_x4[ ((b*4096 + n8)*8 + u)*8 + p ]
//   n8 = n>>3, p = n&7, u = kt2*4 + tg
//   uint4 = { pair(kt=2kt2 ,h=0), pair(kt=2kt2 ,h=1),
//             pair(kt=2kt2+1,h=0), pair(kt=2kt2+1,h=1) }
//   pair(kt,h) = fp16x2 of channels (16kt + 2tg + 8h, +1)
// B layout (uint4): g_b4[ (d*2+kt2)*256 + n*4 + tg ]  (n = out channel)
// ============================================================================

#define NTILES 1024                   // 8 b * 32 t * 4 r-quads
#define GRID   444                    // 148 SMs * 3 CTAs
#define NTHR   128
#define SMEM_BYTES (3584 * 16)        // 56 KB weights

__device__ __align__(16) uint4 g_x4[8u * 4096 * 64];   // 32 MB
__device__ __align__(16) uint4 g_b4[3584];             // 56 KB

// direction order: self, c-, c+, r-, r+, t-, t+  (value = weight index)
__constant__ int c_pd [7] = {0,  5,  6,  3,  4,  1,  2};
__constant__ int c_pdt[7] = {0,  0,  0,  0,  0, -1,  1};
__constant__ int c_pdr[7] = {0,  0,  0, -1,  1,  0,  0};
__constant__ int c_pdc[7] = {0, -1,  1,  0,  0,  0,  0};

static __device__ __forceinline__ void mma_f16(
    float* c, uint32_t a0, uint32_t a1, uint32_t a2, uint32_t a3,
    uint32_t b0, uint32_t b1)
{
    asm volatile(
        "mma.sync.aligned.m16n8k16.row.col.f32.f16.f16.f32 "
        "{%0,%1,%2,%3}, {%4,%5,%6,%7}, {%8,%9}, {%0,%1,%2,%3};"
        : "+f"(c[0]), "+f"(c[1]), "+f"(c[2]), "+f"(c[3])
        : "r"(a0), "r"(a1), "r"(a2), "r"(a3), "r"(b0), "r"(b1));
}

static __device__ __forceinline__ uint32_t packh2(float a, float b) {
    __half2 h = __floats2half2_rn(a, b);
    return *reinterpret_cast<uint32_t*>(&h);
}

// ============================================================================
// k_prep: blocks [0,4096) split x (64-point chunks, SMEM transpose, float4
//         global reads); blocks [4096, 4110) permute weights.
// ============================================================================
__global__ void __launch_bounds__(256) k_prep(
    const float* __restrict__ x,
    const float* __restrict__ w0, const float* __restrict__ w1,
    const float* __restrict__ w2, const float* __restrict__ w3,
    const float* __restrict__ w4, const float* __restrict__ w5,
    const float* __restrict__ w6)
{
    __shared__ float sm[64][68];
    int blk = blockIdx.x;
    int tid = threadIdx.x;

    if (blk < 4096) {
        int b  = blk >> 9;
        int nc = (blk & 511) << 6;                     // chunk base point
        const float* px = x + (((size_t)b) << 21) + nc;
        #pragma unroll
        for (int i = tid; i < 1024; i += 256) {
            int k = i >> 4, q = i & 15;
            float4 v = __ldg((const float4*)(px + (((size_t)k) << 15)) + q);
            *(float4*)&sm[k][q * 4] = v;
        }
        __syncthreads();
        #pragma unroll
        for (int i = tid; i < 512; i += 256) {
            int p   = i & 7;
            int u   = (i >> 3) & 7;
            int np  = ((i >> 6) << 3) | p;
            int kt2 = u >> 2, tg = u & 3;
            int k0  = 32 * kt2 + 2 * tg;
            int k1  = k0 + 16;
            uint4 v;
            v.x = packh2(sm[k0][np],     sm[k0 + 1][np]);
            v.y = packh2(sm[k0 + 8][np], sm[k0 + 9][np]);
            v.z = packh2(sm[k1][np],     sm[k1 + 1][np]);
            v.w = packh2(sm[k1 + 8][np], sm[k1 + 9][np]);
            int n8 = (nc >> 3) + (np >> 3);
            g_x4[((((size_t)b << 12) + n8) << 6) + (u << 3) + p] = v;
        }
    } else {
        int i = (blk - 4096) * 256 + tid;
        if (i < 3584) {
            int d   = i / 512;
            int rem = i & 511;
            int kt2 = rem >> 8;
            int n   = (rem >> 2) & 63;
            int tg  = rem & 3;
            const float* w = (d == 0) ? w0 : (d == 1) ? w1 : (d == 2) ? w2 :
                             (d == 3) ? w3 : (d == 4) ? w4 : (d == 5) ? w5 : w6;
            const float* wr = w + n * 64;
            int k0 = 32 * kt2 + 2 * tg;
            int k1 = k0 + 16;
            uint4 v;
            v.x = packh2(wr[k0],     wr[k0 + 1]);
            v.y = packh2(wr[k0 + 8], wr[k0 + 9]);
            v.z = packh2(wr[k1],     wr[k1 + 1]);
            v.w = packh2(wr[k1 + 8], wr[k1 + 9]);
            g_b4[i] = v;
        }
    }
}

// ============================================================================
// k_gemm: persistent, 444 CTAs x 128 threads, stride-444 over 1024 tiles.
//   Tile = (b, t, 8 r x 32 c) = 256 points; 4 warps, warp M=64 N=64 K=64.
//   A: dense predicated LDG.128 from g_x4; B: dense LDS.128 from SMEM.
//   7 directions accumulate in 128 fp32 regs; rolled d-loop, unrolled kt2.
// ============================================================================
__global__ void __launch_bounds__(NTHR, 3) k_gemm(float* __restrict__ out)
{
    extern __shared__ uint4 sB[];      // 3584 uint4
    const int tid  = threadIdx.x;
    const int w    = tid >> 5;
    const int lane = tid & 31;
    const int g    = lane >> 2;
    const int tg   = lane & 3;

    #pragma unroll
    for (int i = tid; i < 3584; i += NTHR)
        sB[i] = __ldg(g_b4 + i);
    __syncthreads();

    #pragma unroll 1
    for (int tile = blockIdx.x; tile < NTILES; tile += GRID) {
        int rg = tile & 3;
        int t  = (tile >> 2) & 31;
        int b  = tile >> 7;
        int rbase = rg * 8 + w * 2;
        int n0 = t * 1024 + rbase * 32;

        float acc[4][8][4];
        #pragma unroll
        for (int mt = 0; mt < 4; mt++)
            #pragma unroll
            for (int nt = 0; nt < 8; nt++)
                #pragma unroll
                for (int q = 0; q < 4; q++) acc[mt][nt][q] = 0.f;

        #pragma unroll 1
        for (int di = 0; di < 7; ++di) {
            int d  = c_pd[di];
            int ts = t + c_pdt[di];
            int dr = c_pdr[di];
            int dc = c_pdc[di];
            if ((unsigned)ts >= 32u) continue;

            // closed-form addressing: scalar base + per-lane validity mask
            int r0 = rbase + dr;
            bool rv0 = (unsigned)r0 < 32u;
            bool rv1 = (unsigned)(r0 + 1) < 32u;
            int pofs = (dc == 0) ? g
                     : (dc > 0) ? ((g == 7) ? 64 : g + 1)
                                : ((g == 0) ? 7 - 64 : g - 1);
            int base = (((b << 12) + ts * 128 + r0 * 4) << 6) + (tg << 3) + pofs;
            int ck = (dc > 0 && g == 7) ? 3 : ((dc < 0 && g == 0) ? 0 : -1);
            unsigned vm = 0;
            #pragma unroll
            for (int f = 0; f < 8; f++) {
                bool v = ((f >> 2) ? rv1 : rv0) && ((f & 3) != ck);
                vm |= (unsigned)v << f;
            }

            #pragma unroll
            for (int kt2 = 0; kt2 < 2; ++kt2) {
                uint4 A[8];
                const uint4 z4 = make_uint4(0u, 0u, 0u, 0u);
                #pragma unroll
                for (int f = 0; f < 8; f++) {
                    bool v = (vm >> f) & 1u;
                    A[f] = v ? __ldg(g_x4 + (base + (f & 3) * 64
                                             + (f >> 2) * 256 + kt2 * 32))
                             : z4;
                }

                #pragma unroll
                for (int nh = 0; nh < 2; nh++) {
                    #pragma unroll
                    for (int jj = 0; jj < 2; jj++) {
                        uint4 bf0 = sB[(d * 2 + kt2) * 256
                                       + ((nh * 4 + 2 * jj) * 8 + g) * 4 + tg];
                        uint4 bf1 = sB[(d * 2 + kt2) * 256
                                       + ((nh * 4 + 2 * jj + 1) * 8 + g) * 4 + tg];
                        #pragma unroll
                        for (int mt = 0; mt < 4; mt++) {
                            float* a0 = acc[mt][nh * 4 + 2 * jj];
                            mma_f16(a0, A[2*mt].x, A[2*mt+1].x,
                                        A[2*mt].y, A[2*mt+1].y, bf0.x, bf0.y);
                            mma_f16(a0, A[2*mt].z, A[2*mt+1].z,
                                        A[2*mt].w, A[2*mt+1].w, bf0.z, bf0.w);
                            float* a1 = acc[mt][nh * 4 + 2 * jj + 1];
                            mma_f16(a1, A[2*mt].x, A[2*mt+1].x,
                                        A[2*mt].y, A[2*mt+1].y, bf1.x, bf1.y);
                            mma_f16(a1, A[2*mt].z, A[2*mt+1].z,
                                        A[2*mt].w, A[2*mt+1].w, bf1.z, bf1.w);
                        }
                    }
                }
            }
        }

        // epilogue: out[b][o][n0 + m]
        #pragma unroll
        for (int mt = 0; mt < 4; mt++) {
            #pragma unroll
            for (int nt = 0; nt < 8; nt++) {
                int o0 = nt * 8 + tg * 2;
                int m0 = mt * 16 + g;
                float* p = out + ((size_t)(b * 64 + o0) << 15) + n0 + m0;
                p[0]             = acc[mt][nt][0];
                p[1 << 15]       = acc[mt][nt][1];
                p[8]             = acc[mt][nt][2];
                p[(1 << 15) + 8] = acc[mt][nt][3];
            }
        }
    }
}

// ============================================================================
// Launch
// ============================================================================
extern "C" void kernel_launch(void* const* d_in, const int* in_sizes, int n_in,
                              void* d_out, int out_size)
{
    (void)in_sizes; (void)n_in; (void)out_size;
    static bool attr_done = false;
    if (!attr_done) {
        cudaFuncSetAttribute(k_gemm, cudaFuncAttributeMaxDynamicSharedMemorySize,
                             SMEM_BYTES);
        attr_done = true;
    }

    k_prep<<<4096 + 14, 256>>>(
        (const float*)d_in[0],
        (const float*)d_in[1], (const float*)d_in[2], (const float*)d_in[3],
        (const float*)d_in[4], (const float*)d_in[5], (const float*)d_in[6],
        (const float*)d_in[7]);

    k_gemm<<<GRID, NTHR, SMEM_BYTES>>>((float*)d_out);
}

// round 15
// speedup vs baseline: 1.3484x; 1.3484x over previous
#include <cuda_runtime.h>
#include <cuda_fp16.h>
#include <cstdint>

// ============================================================================
// DirectionalConv3d via mma.sync FP16 (compute_103-safe).
//   x: [8, 64, 32, 32, 32] fp32; 7 weights [64,64]; out[b,o,n] =
//     sum_d sum_i W_d[o,i] * x[b,i, n+shift_d]   (zero outside domain)
//
// R14 = proven-best recombination after two falsified experiments:
//   - k_gemm: exact R12-benched 61.3us kernel (128 CTAs x 256 thr, 8 warps,
//     blocked 4-tile assignment, rolled d-loop) -- pipelining (R12 edit) and
//     higher occupancy (R13) both regressed it.
//   - k_prep: R13 float4-read version (measured ~14.7us vs ~22.7us).
//   - epilogue stores use st.global.cs (out is write-once; keep L2 for g_x4).
//
// x scratch layout (uint4 units):  g_x4[ ((b*4096 + n8)*8 + u)*8 + p ]
//   n8 = n>>3, p = n&7, u = kt2*4 + tg
//   uint4 = { pair(kt=2kt2 ,h=0), pair(kt=2kt2 ,h=1),
//             pair(kt=2kt2+1,h=0), pair(kt=2kt2+1,h=1) }
//   pair(kt,h) = fp16x2 of channels (16kt + 2tg + 8h, +1)
// B layout (uint4): g_b4[ (d*2+kt2)*256 + n*4 + tg ]  (n = out channel)
// ============================================================================

#define NTILES 512                    // 8 b * 32 t * 2 r-halves
#define GRID   128                    // 4 consecutive tiles per CTA
#define NTHR   256
#define SMEM_BYTES (3584 * 16)        // 56 KB weights

__device__ __align__(16) uint4 g_x4[8u * 4096 * 64];   // 32 MB
__device__ __align__(16) uint4 g_b4[3584];             // 56 KB

__constant__ int c_dt[7] = {0, -1, 1, 0, 0, 0, 0};
__constant__ int c_dr[7] = {0, 0, 0, -1, 1, 0, 0};
__constant__ int c_dc[7] = {0, 0, 0, 0, 0, -1, 1};

static __device__ __forceinline__ void mma_f16(
    float* c, uint32_t a0, uint32_t a1, uint32_t a2, uint32_t a3,
    uint32_t b0, uint32_t b1)
{
    asm volatile(
        "mma.sync.aligned.m16n8k16.row.col.f32.f16.f16.f32 "
        "{%0,%1,%2,%3}, {%4,%5,%6,%7}, {%8,%9}, {%0,%1,%2,%3};"
        : "+f"(c[0]), "+f"(c[1]), "+f"(c[2]), "+f"(c[3])
        : "r"(a0), "r"(a1), "r"(a2), "r"(a3), "r"(b0), "r"(b1));
}

static __device__ __forceinline__ uint32_t packh2(float a, float b) {
    __half2 h = __floats2half2_rn(a, b);
    return *reinterpret_cast<uint32_t*>(&h);
}

static __device__ __forceinline__ void stcs(float* p, float v) {
    asm volatile("st.global.cs.f32 [%0], %1;" :: "l"(p), "f"(v) : "memory");
}

// ============================================================================
// k_prep: blocks [0,4096) split x (64-point chunks, SMEM transpose, float4
//         global reads); blocks [4096, 4110) permute weights.
// ============================================================================
__global__ void __launch_bounds__(256) k_prep(
    const float* __restrict__ x,
    const float* __restrict__ w0, const float* __restrict__ w1,
    const float* __restrict__ w2, const float* __restrict__ w3,
    const float* __restrict__ w4, const float* __restrict__ w5,
    const float* __restrict__ w6)
{
    __shared__ float sm[64][68];
    int blk = blockIdx.x;
    int tid = threadIdx.x;

    if (blk < 4096) {
        int b  = blk >> 9;
        int nc = (blk & 511) << 6;                     // chunk base point
        const float* px = x + (((size_t)b) << 21) + nc;
        #pragma unroll
        for (int i = tid; i < 1024; i += 256) {
            int k = i >> 4, q = i & 15;
            float4 v = __ldg((const float4*)(px + (((size_t)k) << 15)) + q);
            *(float4*)&sm[k][q * 4] = v;
        }
        __syncthreads();
        #pragma unroll
        for (int i = tid; i < 512; i += 256) {
            int p   = i & 7;
            int u   = (i >> 3) & 7;
            int np  = ((i >> 6) << 3) | p;
            int kt2 = u >> 2, tg = u & 3;
            int k0  = 32 * kt2 + 2 * tg;
            int k1  = k0 + 16;
            uint4 v;
            v.x = packh2(sm[k0][np],     sm[k0 + 1][np]);
            v.y = packh2(sm[k0 + 8][np], sm[k0 + 9][np]);
            v.z = packh2(sm[k1][np],     sm[k1 + 1][np]);
            v.w = packh2(sm[k1 + 8][np], sm[k1 + 9][np]);
            int n8 = (nc >> 3) + (np >> 3);
            g_x4[((((size_t)b << 12) + n8) << 6) + (u << 3) + p] = v;
        }
    } else {
        int i = (blk - 4096) * 256 + tid;
        if (i < 3584) {
            int d   = i / 512;
            int rem = i & 511;
            int kt2 = rem >> 8;
            int n   = (rem >> 2) & 63;
            int tg  = rem & 3;
            const float* w = (d == 0) ? w0 : (d == 1) ? w1 : (d == 2) ? w2 :
                             (d == 3) ? w3 : (d == 4) ? w4 : (d == 5) ? w5 : w6;
            const float* wr = w + n * 64;
            int k0 = 32 * kt2 + 2 * tg;
            int k1 = k0 + 16;
            uint4 v;
            v.x = packh2(wr[k0],     wr[k0 + 1]);
            v.y = packh2(wr[k0 + 8], wr[k0 + 9]);
            v.z = packh2(wr[k1],     wr[k1 + 1]);
            v.w = packh2(wr[k1 + 8], wr[k1 + 9]);
            g_b4[i] = v;
        }
    }
}

// ============================================================================
// k_gemm: persistent, 128 CTAs x 4 consecutive tiles (R12-benched 61.3us).
//   Tile = (b, t, 16 r x 32 c) = 512 points; 8 warps, warp M=64 N=64 K=64.
//   A: dense predicated LDG.128 from g_x4; B: dense LDS.128 from SMEM.
//   7 directions accumulate in 128 fp32 regs; rolled d-loop.
// ============================================================================
__global__ void __launch_bounds__(NTHR, 1) k_gemm(float* __restrict__ out)
{
    extern __shared__ uint4 sB[];      // 3584 uint4
    const int tid  = threadIdx.x;
    const int w    = tid >> 5;
    const int lane = tid & 31;
    const int g    = lane >> 2;
    const int tg   = lane & 3;

    #pragma unroll
    for (int i = tid; i < 3584; i += NTHR)
        sB[i] = __ldg(g_b4 + i);
    __syncthreads();

    for (int it = 0; it < 4; ++it) {
        int tile = blockIdx.x * 4 + it;
        int rq = tile & 1;
        int t  = (tile >> 1) & 31;
        int b  = tile >> 6;
        int rbase = rq * 16 + w * 2;
        int n0 = t * 1024 + rbase * 32;

        float acc[4][8][4];
        #pragma unroll
        for (int mt = 0; mt < 4; mt++)
            #pragma unroll
            for (int nt = 0; nt < 8; nt++)
                #pragma unroll
                for (int q = 0; q < 4; q++) acc[mt][nt][q] = 0.f;

        #pragma unroll 1
        for (int d = 0; d < 7; ++d) {
            int dt = c_dt[d], dr = c_dr[d], dc = c_dc[d];
            int ts = t + dt;
            if ((unsigned)ts >= 32u) continue;

            // per-lane uint4 offsets for the 8 A point-rows (mt x {g, g+8})
            unsigned aoff[4][2];
            bool     aval[4][2];
            #pragma unroll
            for (int mt = 0; mt < 4; mt++) {
                #pragma unroll
                for (int s = 0; s < 2; s++) {
                    int m  = mt * 16 + g + 8 * s;
                    int rs = rbase + (m >> 5) + dr;
                    int cs = (m & 31) + dc;
                    bool v = ((unsigned)rs < 32u) & ((unsigned)cs < 32u);
                    int nsrc = ts * 1024 + rs * 32 + cs;
                    aval[mt][s] = v;
                    aoff[mt][s] = (unsigned)((((b << 12) + (nsrc >> 3)) << 6)
                                             + (tg << 3) + (nsrc & 7));
                }
            }

            #pragma unroll
            for (int kt2 = 0; kt2 < 2; ++kt2) {
                uint4 bf[8];
                #pragma unroll
                for (int nt = 0; nt < 8; nt++)
                    bf[nt] = sB[(d * 2 + kt2) * 256 + (nt * 8 + g) * 4 + tg];

                uint4 A0[4], A1[4];
                const uint4 z4 = make_uint4(0u, 0u, 0u, 0u);
                #pragma unroll
                for (int mt = 0; mt < 4; mt++) {
                    A0[mt] = aval[mt][0] ? __ldg(g_x4 + aoff[mt][0] + kt2 * 32) : z4;
                    A1[mt] = aval[mt][1] ? __ldg(g_x4 + aoff[mt][1] + kt2 * 32) : z4;
                }

                #pragma unroll
                for (int mt = 0; mt < 4; mt++)
                    #pragma unroll
                    for (int nt = 0; nt < 8; nt++) {
                        mma_f16(acc[mt][nt], A0[mt].x, A1[mt].x, A0[mt].y, A1[mt].y,
                                bf[nt].x, bf[nt].y);
                        mma_f16(acc[mt][nt], A0[mt].z, A1[mt].z, A0[mt].w, A1[mt].w,
                                bf[nt].z, bf[nt].w);
                    }
            }
        }

        // epilogue: out[b][o][n0 + m], streaming stores (write-once data)
        #pragma unroll
        for (int mt = 0; mt < 4; mt++) {
            #pragma unroll
            for (int nt = 0; nt < 8; nt++) {
                int o0 = nt * 8 + tg * 2;
                int m0 = mt * 16 + g;
                float* p = out + ((size_t)(b * 64 + o0) << 15) + n0 + m0;
                stcs(p,                acc[mt][nt][0]);
                stcs(p + (1 << 15),    acc[mt][nt][1]);
                stcs(p + 8,            acc[mt][nt][2]);
                stcs(p + (1 << 15) + 8, acc[mt][nt][3]);
            }
        }
    }
}

// ============================================================================
// Launch
// ============================================================================
extern "C" void kernel_launch(void* const* d_in, const int* in_sizes, int n_in,
                              void* d_out, int out_size)
{
    (void)in_sizes; (void)n_in; (void)out_size;
    static bool attr_done = false;
    if (!attr_done) {
        cudaFuncSetAttribute(k_gemm, cudaFuncAttributeMaxDynamicSharedMemorySize,
                             SMEM_BYTES);
        attr_done = true;
    }

    k_prep<<<4096 + 14, 256>>>(
        (const float*)d_in[0],
        (const float*)d_in[1], (const float*)d_in[2], (const float*)d_in[3],
        (const float*)d_in[4], (const float*)d_in[5], (const float*)d_in[6],
        (const float*)d_in[7]);

    k_gemm<<<GRID, NTHR, SMEM_BYTES>>>((float*)d_out);
}

// round 16
// speedup vs baseline: 1.3963x; 1.0355x over previous
#include <cuda_runtime.h>
#include <cuda_fp16.h>
#include <cstdint>

// ============================================================================
// DirectionalConv3d via mma.sync FP16 (compute_103-safe).
//   x: [8, 64, 32, 32, 32] fp32; 7 weights [64,64]; out[b,o,n] =
//     sum_d sum_i W_d[o,i] * x[b,i, n+shift_d]   (zero outside domain)
//
// R15 change vs R14 (76.5us = 61.3 gemm + ~14.5 prep, serialized):
// batch-split stream overlap. prep(b0..3)+weights -> gemm(half1) on stream s1
// while prep(b4..7) runs concurrently on s0; gemm(half2) waits both. Cross-
// stream events become graph edges under capture. k_gemm inner structure is
// byte-identical to the benched 61.3us kernel (now 2 consecutive tiles/CTA).
//
// x scratch layout (uint4 units):  g_x4[ ((b*4096 + n8)*8 + u)*8 + p ]
//   n8 = n>>3, p = n&7, u = kt2*4 + tg
//   uint4 = { pair(kt=2kt2 ,h=0), pair(kt=2kt2 ,h=1),
//             pair(kt=2kt2+1,h=0), pair(kt=2kt2+1,h=1) }
//   pair(kt,h) = fp16x2 of channels (16kt + 2tg + 8h, +1)
// B layout (uint4): g_b4[ (d*2+kt2)*256 + n*4 + tg ]  (n = out channel)
// ============================================================================

#define NTILES 512                    // 8 b * 32 t * 2 r-halves
#define GRID   128                    // CTAs per gemm half (2 tiles each)
#define NTHR   256
#define SMEM_BYTES (3584 * 16)        // 56 KB weights

__device__ __align__(16) uint4 g_x4[8u * 4096 * 64];   // 32 MB
__device__ __align__(16) uint4 g_b4[3584];             // 56 KB

__constant__ int c_dt[7] = {0, -1, 1, 0, 0, 0, 0};
__constant__ int c_dr[7] = {0, 0, 0, -1, 1, 0, 0};
__constant__ int c_dc[7] = {0, 0, 0, 0, 0, -1, 1};

static __device__ __forceinline__ void mma_f16(
    float* c, uint32_t a0, uint32_t a1, uint32_t a2, uint32_t a3,
    uint32_t b0, uint32_t b1)
{
    asm volatile(
        "mma.sync.aligned.m16n8k16.row.col.f32.f16.f16.f32 "
        "{%0,%1,%2,%3}, {%4,%5,%6,%7}, {%8,%9}, {%0,%1,%2,%3};"
        : "+f"(c[0]), "+f"(c[1]), "+f"(c[2]), "+f"(c[3])
        : "r"(a0), "r"(a1), "r"(a2), "r"(a3), "r"(b0), "r"(b1));
}

static __device__ __forceinline__ uint32_t packh2(float a, float b) {
    __half2 h = __floats2half2_rn(a, b);
    return *reinterpret_cast<uint32_t*>(&h);
}

static __device__ __forceinline__ void stcs(float* p, float v) {
    asm volatile("st.global.cs.f32 [%0], %1;" :: "l"(p), "f"(v) : "memory");
}

// ============================================================================
// k_prep: blockIdx.x < 2048 -> x 64-point chunk (xbase + blockIdx.x), SMEM
//         transpose with float4 reads; blockIdx.x >= 2048 -> weight permute
//         (only present in the first half-launch).
// ============================================================================
__global__ void __launch_bounds__(256) k_prep(
    int xbase,
    const float* __restrict__ x,
    const float* __restrict__ w0, const float* __restrict__ w1,
    const float* __restrict__ w2, const float* __restrict__ w3,
    const float* __restrict__ w4, const float* __restrict__ w5,
    const float* __restrict__ w6)
{
    __shared__ float sm[64][68];
    int tid = threadIdx.x;

    if (blockIdx.x < 2048) {
        int blk = xbase + blockIdx.x;
        int b  = blk >> 9;
        int nc = (blk & 511) << 6;                     // chunk base point
        const float* px = x + (((size_t)b) << 21) + nc;
        #pragma unroll
        for (int i = tid; i < 1024; i += 256) {
            int k = i >> 4, q = i & 15;
            float4 v = __ldg((const float4*)(px + (((size_t)k) << 15)) + q);
            *(float4*)&sm[k][q * 4] = v;
        }
        __syncthreads();
        #pragma unroll
        for (int i = tid; i < 512; i += 256) {
            int p   = i & 7;
            int u   = (i >> 3) & 7;
            int np  = ((i >> 6) << 3) | p;
            int kt2 = u >> 2, tg = u & 3;
            int k0  = 32 * kt2 + 2 * tg;
            int k1  = k0 + 16;
            uint4 v;
            v.x = packh2(sm[k0][np],     sm[k0 + 1][np]);
            v.y = packh2(sm[k0 + 8][np], sm[k0 + 9][np]);
            v.z = packh2(sm[k1][np],     sm[k1 + 1][np]);
            v.w = packh2(sm[k1 + 8][np], sm[k1 + 9][np]);
            int n8 = (nc >> 3) + (np >> 3);
            g_x4[((((size_t)b << 12) + n8) << 6) + (u << 3) + p] = v;
        }
    } else {
        int i = (blockIdx.x - 2048) * 256 + tid;
        if (i < 3584) {
            int d   = i / 512;
            int rem = i & 511;
            int kt2 = rem >> 8;
            int n   = (rem >> 2) & 63;
            int tg  = rem & 3;
            const float* w = (d == 0) ? w0 : (d == 1) ? w1 : (d == 2) ? w2 :
                             (d == 3) ? w3 : (d == 4) ? w4 : (d == 5) ? w5 : w6;
            const float* wr = w + n * 64;
            int k0 = 32 * kt2 + 2 * tg;
            int k1 = k0 + 16;
            uint4 v;
            v.x = packh2(wr[k0],     wr[k0 + 1]);
            v.y = packh2(wr[k0 + 8], wr[k0 + 9]);
            v.z = packh2(wr[k1],     wr[k1 + 1]);
            v.w = packh2(wr[k1 + 8], wr[k1 + 9]);
            g_b4[i] = v;
        }
    }
}

// ============================================================================
// k_gemm: 128 CTAs x 2 consecutive tiles, tile_base selects the batch half.
//   Tile = (b, t, 16 r x 32 c) = 512 points; 8 warps, warp M=64 N=64 K=64.
//   A: dense predicated LDG.128 from g_x4; B: dense LDS.128 from SMEM.
//   7 directions accumulate in 128 fp32 regs; rolled d-loop. (R12 structure.)
// ============================================================================
__global__ void __launch_bounds__(NTHR, 1) k_gemm(float* __restrict__ out,
                                                  int tile_base)
{
    extern __shared__ uint4 sB[];      // 3584 uint4
    const int tid  = threadIdx.x;
    const int w    = tid >> 5;
    const int lane = tid & 31;
    const int g    = lane >> 2;
    const int tg   = lane & 3;

    #pragma unroll
    for (int i = tid; i < 3584; i += NTHR)
        sB[i] = __ldg(g_b4 + i);
    __syncthreads();

    for (int it = 0; it < 2; ++it) {
        int tile = tile_base + blockIdx.x * 2 + it;
        int rq = tile & 1;
        int t  = (tile >> 1) & 31;
        int b  = tile >> 6;
        int rbase = rq * 16 + w * 2;
        int n0 = t * 1024 + rbase * 32;

        float acc[4][8][4];
        #pragma unroll
        for (int mt = 0; mt < 4; mt++)
            #pragma unroll
            for (int nt = 0; nt < 8; nt++)
                #pragma unroll
                for (int q = 0; q < 4; q++) acc[mt][nt][q] = 0.f;

        #pragma unroll 1
        for (int d = 0; d < 7; ++d) {
            int dt = c_dt[d], dr = c_dr[d], dc = c_dc[d];
            int ts = t + dt;
            if ((unsigned)ts >= 32u) continue;

            // per-lane uint4 offsets for the 8 A point-rows (mt x {g, g+8})
            unsigned aoff[4][2];
            bool     aval[4][2];
            #pragma unroll
            for (int mt = 0; mt < 4; mt++) {
                #pragma unroll
                for (int s = 0; s < 2; s++) {
                    int m  = mt * 16 + g + 8 * s;
                    int rs = rbase + (m >> 5) + dr;
                    int cs = (m & 31) + dc;
                    bool v = ((unsigned)rs < 32u) & ((unsigned)cs < 32u);
                    int nsrc = ts * 1024 + rs * 32 + cs;
                    aval[mt][s] = v;
                    aoff[mt][s] = (unsigned)((((b << 12) + (nsrc >> 3)) << 6)
                                             + (tg << 3) + (nsrc & 7));
                }
            }

            #pragma unroll
            for (int kt2 = 0; kt2 < 2; ++kt2) {
                uint4 bf[8];
                #pragma unroll
                for (int nt = 0; nt < 8; nt++)
                    bf[nt] = sB[(d * 2 + kt2) * 256 + (nt * 8 + g) * 4 + tg];

                uint4 A0[4], A1[4];
                const uint4 z4 = make_uint4(0u, 0u, 0u, 0u);
                #pragma unroll
                for (int mt = 0; mt < 4; mt++) {
                    A0[mt] = aval[mt][0] ? __ldg(g_x4 + aoff[mt][0] + kt2 * 32) : z4;
                    A1[mt] = aval[mt][1] ? __ldg(g_x4 + aoff[mt][1] + kt2 * 32) : z4;
                }

                #pragma unroll
                for (int mt = 0; mt < 4; mt++)
                    #pragma unroll
                    for (int nt = 0; nt < 8; nt++) {
                        mma_f16(acc[mt][nt], A0[mt].x, A1[mt].x, A0[mt].y, A1[mt].y,
                                bf[nt].x, bf[nt].y);
                        mma_f16(acc[mt][nt], A0[mt].z, A1[mt].z, A0[mt].w, A1[mt].w,
                                bf[nt].z, bf[nt].w);
                    }
            }
        }

        // epilogue: out[b][o][n0 + m], streaming stores (write-once data)
        #pragma unroll
        for (int mt = 0; mt < 4; mt++) {
            #pragma unroll
            for (int nt = 0; nt < 8; nt++) {
                int o0 = nt * 8 + tg * 2;
                int m0 = mt * 16 + g;
                float* p = out + ((size_t)(b * 64 + o0) << 15) + n0 + m0;
                stcs(p,                 acc[mt][nt][0]);
                stcs(p + (1 << 15),     acc[mt][nt][1]);
                stcs(p + 8,             acc[mt][nt][2]);
                stcs(p + (1 << 15) + 8, acc[mt][nt][3]);
            }
        }
    }
}

// ============================================================================
// Launch: batch-split overlap via a second stream + events (graph-capturable:
// event record/wait become graph edges; stream/event creation is one-time
// host-side setup, no device memory involved).
// ============================================================================
extern "C" void kernel_launch(void* const* d_in, const int* in_sizes, int n_in,
                              void* d_out, int out_size)
{
    (void)in_sizes; (void)n_in; (void)out_size;
    static cudaStream_t s1;
    static cudaEvent_t ev1, ev2, ev3;
    static bool init_done = false;
    if (!init_done) {
        cudaFuncSetAttribute(k_gemm, cudaFuncAttributeMaxDynamicSharedMemorySize,
                             SMEM_BYTES);
        cudaStreamCreateWithFlags(&s1, cudaStreamNonBlocking);
        cudaEventCreateWithFlags(&ev1, cudaEventDisableTiming);
        cudaEventCreateWithFlags(&ev2, cudaEventDisableTiming);
        cudaEventCreateWithFlags(&ev3, cudaEventDisableTiming);
        init_done = true;
    }

    const float* x  = (const float*)d_in[0];
    const float* w0 = (const float*)d_in[1];
    const float* w1 = (const float*)d_in[2];
    const float* w2 = (const float*)d_in[3];
    const float* w3 = (const float*)d_in[4];
    const float* w4 = (const float*)d_in[5];
    const float* w5 = (const float*)d_in[6];
    const float* w6 = (const float*)d_in[7];
    float* out = (float*)d_out;

    // s0 (default stream): prep weights + batches 0..3
    k_prep<<<2048 + 14, 256>>>(0, x, w0, w1, w2, w3, w4, w5, w6);
    cudaEventRecord(ev1, 0);

    // s1: gemm half 1 (tiles 0..255, b 0..3) after prep half 1
    cudaStreamWaitEvent(s1, ev1, 0);
    k_gemm<<<GRID, NTHR, SMEM_BYTES, s1>>>(out, 0);

    // s0 concurrently: prep batches 4..7
    k_prep<<<2048, 256>>>(2048, x, w0, w1, w2, w3, w4, w5, w6);
    cudaEventRecord(ev2, 0);

    // s1: gemm half 2 (tiles 256..511, b 4..7) after prep half 2
    cudaStreamWaitEvent(s1, ev2, 0);
    k_gemm<<<GRID, NTHR, SMEM_BYTES, s1>>>(out, 256);

    // join s1 back into s0 (required for valid capture and correct ordering)
    cudaEventRecord(ev3, s1);
    cudaStreamWaitEvent(0, ev3, 0);
}